// round 16
// baseline (speedup 1.0000x reference)
#include <cuda_runtime.h>
#include <math.h>

#define Bq 128
#define Tq 800
#define Eq 100
#define Hq 96
#define H3 288
#define Rq 12
#define Cq 50
#define Oq 16
#define BT (Bq*Tq)

typedef unsigned long long ull;

__device__ __forceinline__ ull ffma2(ull a, ull b, ull c) {
    ull d;
    asm("fma.rn.f32x2 %0, %1, %2, %3;" : "=l"(d) : "l"(a), "l"(b), "l"(c));
    return d;
}
__device__ __forceinline__ ull pack2(float x, float y) {
    ull r; asm("mov.b64 %0, {%1,%2};" : "=l"(r) : "f"(x), "f"(y)); return r;
}
__device__ __forceinline__ float2 unpack2(ull v) {
    float2 f; asm("mov.b64 {%0,%1}, %2;" : "=f"(f.x), "=f"(f.y) : "l"(v)); return f;
}
__device__ __forceinline__ float exp2_ap(float x){ float y; asm("ex2.approx.f32 %0,%1;":"=f"(y):"f"(x)); return y; }
__device__ __forceinline__ float rcp_ap(float x){ float y; asm("rcp.approx.f32 %0,%1;":"=f"(y):"f"(x)); return y; }
__device__ __forceinline__ float sigm_f(float x){ return rcp_ap(1.f + exp2_ap(-1.4426950409f*x)); }
__device__ __forceinline__ float tanh_f(float x){
    float t = exp2_ap(2.8853900818f*x);
    return 1.f - 2.f*rcp_ap(t + 1.f);
}

// ---------------- static device scratch (no allocations) -------------------
__device__ float g_gi[2][BT][H3];
__device__ float g_h[BT][2*Hq];
__device__ float g_v0T[Rq*2*Hq][Bq];     // [r*192+k][b]
__device__ float g_attreg[Bq];
__device__ float g_uhat[Bq][Rq*Cq*Oq];

// ===========================================================================
// Kernel A: gi = emb[tok] @ wih^T + bih. grid(200,2dir), 256 thr, f32x2.
// Weights staged ONCE per CTA; loop over 8 row-tiles of 64 (R9 inner compute).
// ===========================================================================
__global__ __launch_bounds__(256) void kA(const int* __restrict__ tokens,
                                          const float* __restrict__ emb,
                                          const float* __restrict__ wih_f,
                                          const float* __restrict__ bih_f,
                                          const float* __restrict__ wih_b,
                                          const float* __restrict__ bih_b)
{
    extern __shared__ float sm[];
    float* s_w = sm;               // 100*290
    float* s_x = sm + 100*290;     // 64*100
    __shared__ int s_tok[64];

    const int dir = blockIdx.y;
    const float* wih = dir ? wih_b : wih_f;
    const float* bih = dir ? bih_b : bih_f;
    const int tid = threadIdx.x;
    const int lane = tid & 31, w = tid >> 5;

    for (int i = tid; i < H3*Eq; i += 256) {
        int j = i / Eq, k = i - j*Eq;
        int p = j >> 5, l = j & 31;
        int idx = (p < 8) ? (k*290 + (p>>1)*64 + l*2 + (p&1)) : (k*290 + 256 + l);
        s_w[idx] = wih[i];
    }
    float bb[9];
#pragma unroll
    for (int p = 0; p < 9; p++) bb[p] = bih[p*32 + lane];

    for (int tile = 0; tile < 8; tile++) {
        const int row0 = (blockIdx.x*8 + tile)*64;
        __syncthreads();               // prev tile's s_x/s_tok reads done
        if (tid < 64) s_tok[tid] = tokens[row0 + tid];
        __syncthreads();
        for (int i = tid; i < 64*Eq; i += 256) {
            int r = i / Eq, k = i - r*Eq;
            s_x[i] = emb[(long long)s_tok[r]*Eq + k];
        }
        __syncthreads();

        ull acc2[8][4];
        float acc1[8];
#pragma unroll
        for (int r = 0; r < 8; r++) {
            acc1[r] = 0.f;
#pragma unroll
            for (int pr = 0; pr < 4; pr++) acc2[r][pr] = 0ull;
        }

        const float* xb = s_x + (w*8)*Eq;
        for (int k = 0; k < Eq; k++) {
            const float* wr = s_w + k*290;
            ull wp0 = *(const ull*)&wr[lane*2];
            ull wp1 = *(const ull*)&wr[64 + lane*2];
            ull wp2 = *(const ull*)&wr[128 + lane*2];
            ull wp3 = *(const ull*)&wr[192 + lane*2];
            float w8 = wr[256 + lane];
#pragma unroll
            for (int r = 0; r < 8; r++) {
                float xv = xb[r*Eq + k];
                ull xd = pack2(xv, xv);
                acc2[r][0] = ffma2(xd, wp0, acc2[r][0]);
                acc2[r][1] = ffma2(xd, wp1, acc2[r][1]);
                acc2[r][2] = ffma2(xd, wp2, acc2[r][2]);
                acc2[r][3] = ffma2(xd, wp3, acc2[r][3]);
                acc1[r] = fmaf(xv, w8, acc1[r]);
            }
        }
#pragma unroll
        for (int r = 0; r < 8; r++) {
            float* go = &g_gi[dir][row0 + w*8 + r][0];
#pragma unroll
            for (int pr = 0; pr < 4; pr++) {
                float2 f = unpack2(acc2[r][pr]);
                go[(2*pr)*32 + lane]   = f.x + bb[2*pr];
                go[(2*pr+1)*32 + lane] = f.y + bb[2*pr+1];
            }
            go[256 + lane] = acc1[r] + bb[8];
        }
    }
}

// ===========================================================================
// Kernel B (unchanged from R11): 128-step GRU scan. 148 CTAs, 128 thr.
// ===========================================================================
template<int NR>
__device__ __forceinline__ void gru_rows(const float* __restrict__ s_whh,
                                         const float* __restrict__ s_bhh,
                                         float* __restrict__ s_h,
                                         int lr0, int t0, int dir, int lane)
{
    ull bh[4]; float bh8;
#pragma unroll
    for (int pr = 0; pr < 4; pr++)
        bh[pr] = pack2(s_bhh[(2*pr)*32 + lane], s_bhh[(2*pr+1)*32 + lane]);
    bh8 = s_bhh[256 + lane];

    for (int s = 0; s < Bq; s++) {
        const int b_eff = dir ? (Bq - 1 - s) : s;
        float gir[NR][9];
#pragma unroll
        for (int j = 0; j < NR; j++) {
            const float* gr = &g_gi[dir][b_eff*Tq + t0 + j][0] + lane;
#pragma unroll
            for (int p = 0; p < 9; p++) gir[j][p] = gr[p*32];
        }

        ull acc2[NR][4];
        float acc1[NR];
#pragma unroll
        for (int j = 0; j < NR; j++) {
            acc1[j] = bh8;
#pragma unroll
            for (int pr = 0; pr < 4; pr++) acc2[j][pr] = bh[pr];
        }

        for (int k0 = 0; k0 < Hq; k0 += 4) {
            float4 h4[NR];
#pragma unroll
            for (int j = 0; j < NR; j++)
                h4[j] = *(const float4*)&s_h[(lr0 + j)*Hq + k0];
#pragma unroll
            for (int kk = 0; kk < 4; kk++) {
                const float* wr = s_whh + (k0 + kk)*290;
                ull wp0 = *(const ull*)&wr[lane*2];
                ull wp1 = *(const ull*)&wr[64 + lane*2];
                ull wp2 = *(const ull*)&wr[128 + lane*2];
                ull wp3 = *(const ull*)&wr[192 + lane*2];
                float w8 = wr[256 + lane];
#pragma unroll
                for (int j = 0; j < NR; j++) {
                    float hv = ((const float*)&h4[j])[kk];
                    ull hd = pack2(hv, hv);
                    acc2[j][0] = ffma2(hd, wp0, acc2[j][0]);
                    acc2[j][1] = ffma2(hd, wp1, acc2[j][1]);
                    acc2[j][2] = ffma2(hd, wp2, acc2[j][2]);
                    acc2[j][3] = ffma2(hd, wp3, acc2[j][3]);
                    acc1[j] = fmaf(hv, w8, acc1[j]);
                }
            }
        }
        __syncwarp();
#pragma unroll
        for (int j = 0; j < NR; j++) {
            float a9[9];
#pragma unroll
            for (int pr = 0; pr < 4; pr++) {
                float2 f = unpack2(acc2[j][pr]);
                a9[2*pr] = f.x; a9[2*pr+1] = f.y;
            }
            a9[8] = acc1[j];
            const int lr = lr0 + j;
            float* hout = &g_h[b_eff*Tq + t0 + j][dir*Hq];
#pragma unroll
            for (int g = 0; g < 3; g++) {
                const int u = g*32 + lane;
                float rg = sigm_f(gir[j][g]   + a9[g]);
                float zg = sigm_f(gir[j][3+g] + a9[3+g]);
                float ng = tanh_f(gir[j][6+g] + rg*a9[6+g]);
                float ho = s_h[lr*Hq + u];
                float h2 = ng + zg*(ho - ng);
                s_h[lr*Hq + u] = h2;
                hout[u] = h2;
            }
        }
        __syncwarp();
    }
}

__global__ __launch_bounds__(128) void kB(const float* __restrict__ whh_f,
                                          const float* __restrict__ bhh_f,
                                          const float* __restrict__ whh_b,
                                          const float* __restrict__ bhh_b)
{
    extern __shared__ float sm[];
    float* s_whh = sm;                 // 96*290
    float* s_bhh = sm + Hq*290;        // 288
    float* s_h   = s_bhh + H3;         // 12*96
    const int dir = blockIdx.x / 74;
    const int ci  = blockIdx.x % 74;
    const int base  = ci*10 + (ci < 60 ? ci : 60);
    const int count = 10 + (ci < 60 ? 1 : 0);
    const float* whh = dir ? whh_b : whh_f;
    const float* bhh = dir ? bhh_b : bhh_f;
    const int tid = threadIdx.x;

    for (int i = tid; i < H3*Hq; i += 128) {
        int j = i / Hq, k = i - j*Hq;
        int p = j >> 5, l = j & 31;
        int idx = (p < 8) ? (k*290 + (p>>1)*64 + l*2 + (p&1)) : (k*290 + 256 + l);
        s_whh[idx] = whh[i];
    }
    for (int i = tid; i < H3; i += 128) s_bhh[i] = bhh[i];
    for (int i = tid; i < 12*Hq; i += 128) s_h[i] = 0.f;
    __syncthreads();

    const int w = tid >> 5, lane = tid & 31;
    const int q = count >> 2, rem = count & 3;
    const int w_off = w*q + (w < rem ? w : rem);
    const int nr = q + (w < rem ? 1 : 0);
    if (nr == 3) gru_rows<3>(s_whh, s_bhh, s_h, w_off, base + w_off, dir, lane);
    else         gru_rows<2>(s_whh, s_bhh, s_h, w_off, base + w_off, dir, lane);
}

// ===========================================================================
// Kernel C: attention + m + gram + squash -> v0T, attreg. 128 CTAs, 256 thr.
// h tile stored TRANSPOSED s_hT[k][row] (pitch 66) -> GEMM1 row-pair operand
// is one broadcast LDS.64.
// ===========================================================================
__global__ __launch_bounds__(256) void kC(const float* __restrict__ A1,
                                          const float* __restrict__ b1,
                                          const float* __restrict__ A2,
                                          const float* __restrict__ b2)
{
    extern __shared__ float sm[];
    float* A1s = sm;                       // 9600
    float* A2s = A1s + 9600;               // 600
    float* b1s = A2s + 600;                // 52
    float* b2s = b1s + 52;                 // 16
    float* s_hT = b2s + 16;                // 192*66 = 12672  [k][row], pitch 66
    float* s_P  = s_hT + 12672;            // 64*53
    float* s_a  = s_P + 3392;              // 64*12
    float* m_s  = s_a + 768;               // 2304
    float* G_s  = m_s + 2304;              // 144

    const int b = blockIdx.x, tid = threadIdx.x;
    const int lane = tid & 31, w = tid >> 5;

    for (int i = tid; i < 9600; i += 256) A1s[i] = A1[i];
    for (int i = tid; i < 600;  i += 256) A2s[i] = A2[i];
    if (tid < 50) b1s[tid] = b1[tid];
    if (tid < 12) b2s[tid] = b2[tid];
    if (tid < 144) G_s[tid] = 0.f;

    float accm[12];
#pragma unroll
    for (int r = 0; r < 12; r++) accm[r] = 0.f;

    for (int t0 = 0; t0 < Tq; t0 += 64) {
        const int nrows = (Tq - t0 < 64) ? (Tq - t0) : 64;
        __syncthreads();
        const float4* h4s = (const float4*)&g_h[b*Tq + t0][0];
        for (int i = tid; i < nrows*48; i += 256) {
            int row = i / 48, k4 = i - row*48;
            float4 v = h4s[i];
            float* dst = s_hT + (k4*4)*66 + row;
            dst[0]   = v.x;
            dst[66]  = v.y;
            dst[132] = v.z;
            dst[198] = v.w;
        }
        __syncthreads();

        // GEMM1: P = tanh(h @ A1 + b1), row pairs via f32x2; h pair = LDS.64 bcast
        {
            const int rbase = w*8;
            if (rbase < nrows) {
                ull acc0p[4], acc1p[4];
#pragma unroll
                for (int pr = 0; pr < 4; pr++) { acc0p[pr] = 0ull; acc1p[pr] = 0ull; }
                for (int k = 0; k < 192; k++) {
                    float a0 = A1s[k*50 + lane];
                    float a1 = (lane < 18) ? A1s[k*50 + lane + 32] : 0.f;
                    ull a0d = pack2(a0, a0), a1d = pack2(a1, a1);
                    const ull* hrow = (const ull*)(s_hT + k*66 + rbase);
#pragma unroll
                    for (int pr = 0; pr < 4; pr++) {
                        ull hp = hrow[pr];
                        acc0p[pr] = ffma2(hp, a0d, acc0p[pr]);
                        acc1p[pr] = ffma2(hp, a1d, acc1p[pr]);
                    }
                }
#pragma unroll
                for (int pr = 0; pr < 4; pr++) {
                    float2 f0 = unpack2(acc0p[pr]);
                    float2 f1 = unpack2(acc1p[pr]);
                    int r0 = rbase + 2*pr, r1 = r0 + 1;
                    if (r0 < nrows) {
                        s_P[r0*53 + lane] = tanh_f(f0.x + b1s[lane]);
                        if (lane < 18) s_P[r0*53 + lane + 32] = tanh_f(f1.x + b1s[lane+32]);
                    }
                    if (r1 < nrows) {
                        s_P[r1*53 + lane] = tanh_f(f0.y + b1s[lane]);
                        if (lane < 18) s_P[r1*53 + lane + 32] = tanh_f(f1.y + b1s[lane+32]);
                    }
                }
            }
        }
        __syncthreads();

        for (int i = tid; i < nrows*12; i += 256) {
            int t = i / 12, r = i - t*12;
            float s = b2s[r];
            for (int k = 0; k < 50; k++) s = fmaf(s_P[t*53 + k], A2s[k*12 + r], s);
            s_a[t*12 + r] = s;
        }
        __syncthreads();

        if (tid < nrows) {
            float* ar = s_a + tid*12;
            float mx = ar[0];
#pragma unroll
            for (int r = 1; r < 12; r++) mx = fmaxf(mx, ar[r]);
            float ss = 0.f;
#pragma unroll
            for (int r = 0; r < 12; r++) { float e = __expf(ar[r]-mx); ar[r] = e; ss += e; }
            float inv = 1.f/ss;
#pragma unroll
            for (int r = 0; r < 12; r++) ar[r] *= inv;
        }
        __syncthreads();

        if (tid < 192) {
            for (int lt = 0; lt < nrows; lt++) {
                float hv = s_hT[tid*66 + lt];
                const float4* a4 = (const float4*)(s_a + lt*12);
                float4 c0 = a4[0], c1 = a4[1], c2 = a4[2];
                accm[0]  = fmaf(c0.x, hv, accm[0]);
                accm[1]  = fmaf(c0.y, hv, accm[1]);
                accm[2]  = fmaf(c0.z, hv, accm[2]);
                accm[3]  = fmaf(c0.w, hv, accm[3]);
                accm[4]  = fmaf(c1.x, hv, accm[4]);
                accm[5]  = fmaf(c1.y, hv, accm[5]);
                accm[6]  = fmaf(c1.z, hv, accm[6]);
                accm[7]  = fmaf(c1.w, hv, accm[7]);
                accm[8]  = fmaf(c2.x, hv, accm[8]);
                accm[9]  = fmaf(c2.y, hv, accm[9]);
                accm[10] = fmaf(c2.z, hv, accm[10]);
                accm[11] = fmaf(c2.w, hv, accm[11]);
            }
        } else {
            for (int ii = tid - 192; ii < 144; ii += 64) {
                int r = ii / 12, s2 = ii - r*12;
                float g = 0.f;
                for (int lt = 0; lt < nrows; lt++)
                    g = fmaf(s_a[lt*12 + r], s_a[lt*12 + s2], g);
                G_s[ii] += g;
            }
        }
    }
    __syncthreads();
    if (tid < 192)
#pragma unroll
        for (int r = 0; r < 12; r++) m_s[r*192 + tid] = accm[r];
    __syncthreads();

    for (int r = w; r < 12; r += 8) {
        float s = 0.f;
        for (int k = lane; k < 192; k += 32) { float x = m_s[r*192+k]; s = fmaf(x,x,s); }
#pragma unroll
        for (int off = 16; off; off >>= 1) s += __shfl_xor_sync(0xffffffffu, s, off);
        float sc = s/(s + 1.f)*rsqrtf(s);
        for (int k = lane; k < 192; k += 32)
            g_v0T[r*192 + k][b] = m_s[r*192+k]*sc;
    }
    if (tid < 144) {
        int r = tid / 12, s2 = tid - r*12;
        float d = G_s[tid] - (r == s2 ? 1.f : 0.f);
        G_s[tid] = d*d;
    }
    __syncthreads();
    if (tid == 0) {
        float s = 0.f;
        for (int i = 0; i < 144; i++) s += G_s[i];
        g_attreg[b] = sqrtf(s);
    }
}

// ===========================================================================
// Kernel D (unchanged): u_hat = v0 @ Wcaps per r. grid(20,12), 256 thr, f32x2.
// ===========================================================================
__global__ __launch_bounds__(256) void kD(const float* __restrict__ Wcaps)
{
    extern __shared__ float sm[];
    float* s_w = sm;                // 192*40
    float* s_v = sm + 192*40;       // 64*128
    const int cch = blockIdx.x, r = blockIdx.y;
    const int tid = threadIdx.x;
    const int b = tid & 127, half = tid >> 7;
    const int lane = tid & 31, w = tid >> 5;

    for (int k = w; k < 192; k += 8) {
        const float* src = Wcaps + (long long)(r*192 + k)*800 + cch*40;
        for (int off = lane; off < 40; off += 32) s_w[k*40 + off] = src[off];
    }

    ull acc2[10];
#pragma unroll
    for (int q = 0; q < 10; q++) acc2[q] = 0ull;

    for (int kc = 0; kc < 3; kc++) {
        __syncthreads();
        for (int i = tid; i < 64*128; i += 256)
            s_v[i] = g_v0T[r*192 + kc*64 + (i >> 7)][i & 127];
        __syncthreads();
#pragma unroll 4
        for (int k2 = 0; k2 < 64; k2++) {
            float vv = s_v[k2*128 + b];
            ull vd = pack2(vv, vv);
            const ulonglong2* w2 = (const ulonglong2*)(s_w + (kc*64 + k2)*40 + half*20);
#pragma unroll
            for (int q = 0; q < 5; q++) {
                ulonglong2 wv = w2[q];
                acc2[2*q]   = ffma2(vd, wv.x, acc2[2*q]);
                acc2[2*q+1] = ffma2(vd, wv.y, acc2[2*q+1]);
            }
        }
    }
    float* up = &g_uhat[b][r*800 + cch*40 + half*20];
#pragma unroll
    for (int q = 0; q < 10; q++) {
        float2 f = unpack2(acc2[q]);
        up[2*q] = f.x; up[2*q+1] = f.y;
    }
}

// ===========================================================================
// Kernel E (unchanged): 3-iter dynamic routing in smem + output. 128 CTAs.
// ===========================================================================
__global__ __launch_bounds__(256) void kE(float* __restrict__ out, int out_size)
{
    extern __shared__ float sm[];
    float* u   = sm;            // 9600
    float* bl  = u + 9600;      // 600
    float* cc  = bl + 600;      // 600
    float* s_s = cc + 600;      // 800
    float* s_v = s_s + 800;     // 800
    float* s_n = s_v + 800;     // 50

    const int b = blockIdx.x, tid = threadIdx.x;
    const float4* u4 = (const float4*)&g_uhat[b][0];
    float4* su4 = (float4*)u;
    for (int i = tid; i < 2400; i += 256) su4[i] = u4[i];
    for (int i = tid; i < 600; i += 256) bl[i] = 0.f;
    __syncthreads();

    for (int it = 0; it < 3; it++) {
        if (tid < 12) {
            const float* br = bl + tid*50;
            float mx = br[0];
            for (int k = 1; k < 50; k++) mx = fmaxf(mx, br[k]);
            float ss = 0.f;
            for (int k = 0; k < 50; k++) { float e = __expf(br[k]-mx); cc[tid*50+k] = e; ss += e; }
            float inv = 1.f/ss;
            for (int k = 0; k < 50; k++) cc[tid*50+k] *= inv;
        }
        __syncthreads();
        for (int i = tid; i < 800; i += 256) {
            int ci = i >> 4, o = i & 15;
            float s = 0.f;
#pragma unroll
            for (int r = 0; r < 12; r++)
                s = fmaf(cc[r*50 + ci], u[(r*50 + ci)*16 + o], s);
            s_s[i] = s;
        }
        __syncthreads();
        if (tid < 50) {
            float n = 0.f;
#pragma unroll
            for (int o = 0; o < 16; o++) { float x = s_s[tid*16+o]; n = fmaf(x,x,n); }
            s_n[tid] = n/(n + 1.f)*rsqrtf(n);
        }
        __syncthreads();
        for (int i = tid; i < 800; i += 256) s_v[i] = s_s[i]*s_n[i >> 4];
        __syncthreads();
        if (it != 2) {
            for (int i = tid; i < 600; i += 256) {
                int r = i / 50, ci = i - r*50;
                float s = 0.f;
#pragma unroll
                for (int o = 0; o < 16; o++)
                    s = fmaf(u[(r*50 + ci)*16 + o], s_v[ci*16 + o], s);
                bl[i] += s;
            }
            __syncthreads();
        }
    }
    for (int i = tid; i < 800; i += 256) out[b*800 + i] = s_v[i];

    if (b == 0 && tid == 0 && out_size > Bq*800) {
        float s = 0.f;
        for (int i = 0; i < Bq; i++) s += g_attreg[i];
        out[Bq*800] = s / Bq;
    }
}

// ===========================================================================
extern "C" void kernel_launch(void* const* d_in, const int* in_sizes, int n_in,
                              void* d_out, int out_size)
{
    const int*   tokens = (const int*)  d_in[0];
    const float* emb    = (const float*)d_in[1];
    const float* wih_f  = (const float*)d_in[2];
    const float* whh_f  = (const float*)d_in[3];
    const float* bih_f  = (const float*)d_in[4];
    const float* bhh_f  = (const float*)d_in[5];
    const float* wih_b  = (const float*)d_in[6];
    const float* whh_b  = (const float*)d_in[7];
    const float* bih_b  = (const float*)d_in[8];
    const float* bhh_b  = (const float*)d_in[9];
    const float* A1     = (const float*)d_in[10];
    const float* b1     = (const float*)d_in[11];
    const float* A2     = (const float*)d_in[12];
    const float* b2     = (const float*)d_in[13];
    const float* Wcaps  = (const float*)d_in[14];
    float* out = (float*)d_out;

    const int smA = (100*290 + 64*100)*4;
    const int smB = (96*290 + 288 + 12*96)*4;
    const int smC = (9600+600+52+16+12672+3392+768+2304+144)*4;
    const int smD = (192*40 + 64*128)*4;
    const int smE = (9600+600+600+800+800+50)*4;

    cudaFuncSetAttribute(kA, cudaFuncAttributeMaxDynamicSharedMemorySize, smA);
    cudaFuncSetAttribute(kB, cudaFuncAttributeMaxDynamicSharedMemorySize, smB);
    cudaFuncSetAttribute(kC, cudaFuncAttributeMaxDynamicSharedMemorySize, smC);
    cudaFuncSetAttribute(kD, cudaFuncAttributeMaxDynamicSharedMemorySize, smD);
    cudaFuncSetAttribute(kE, cudaFuncAttributeMaxDynamicSharedMemorySize, smE);

    kA<<<dim3(200, 2), 256, smA>>>(tokens, emb, wih_f, bih_f, wih_b, bih_b);
    kB<<<148, 128, smB>>>(whh_f, bhh_f, whh_b, bhh_b);
    kC<<<128, 256, smC>>>(A1, b1, A2, b2);
    kD<<<dim3(20, 12), 256, smD>>>(Wcaps);
    kE<<<128, 256, smE>>>(out, out_size);
}

// round 17
// speedup vs baseline: 1.0017x; 1.0017x over previous
#include <cuda_runtime.h>
#include <math.h>

#define Bq 128
#define Tq 800
#define Eq 100
#define Hq 96
#define H3 288
#define Rq 12
#define Cq 50
#define Oq 16
#define BT (Bq*Tq)

typedef unsigned long long ull;

__device__ __forceinline__ ull ffma2(ull a, ull b, ull c) {
    ull d;
    asm("fma.rn.f32x2 %0, %1, %2, %3;" : "=l"(d) : "l"(a), "l"(b), "l"(c));
    return d;
}
__device__ __forceinline__ ull pack2(float x, float y) {
    ull r; asm("mov.b64 %0, {%1,%2};" : "=l"(r) : "f"(x), "f"(y)); return r;
}
__device__ __forceinline__ float2 unpack2(ull v) {
    float2 f; asm("mov.b64 {%0,%1}, %2;" : "=f"(f.x), "=f"(f.y) : "l"(v)); return f;
}
__device__ __forceinline__ float exp2_ap(float x){ float y; asm("ex2.approx.f32 %0,%1;":"=f"(y):"f"(x)); return y; }
__device__ __forceinline__ float rcp_ap(float x){ float y; asm("rcp.approx.f32 %0,%1;":"=f"(y):"f"(x)); return y; }
__device__ __forceinline__ float sigm_f(float x){ return rcp_ap(1.f + exp2_ap(-1.4426950409f*x)); }
__device__ __forceinline__ float tanh_f(float x){
    float t = exp2_ap(2.8853900818f*x);
    return 1.f - 2.f*rcp_ap(t + 1.f);
}

// ---------------- static device scratch (no allocations) -------------------
__device__ float g_gi[2][BT][H3];
__device__ float g_h[BT][2*Hq];
__device__ float g_v0T[Rq*2*Hq][Bq];     // [r*192+k][b]
__device__ float g_attreg[Bq];
__device__ float g_uhat[Bq][Rq*Cq*Oq];

// ===========================================================================
// Kernel A: gi = emb[tok] @ wih^T + bih. grid(200,2dir), 256 thr, f32x2.
// Weights staged ONCE per CTA; loop over 8 row-tiles of 64 (R9 inner compute).
// ===========================================================================
__global__ __launch_bounds__(256) void kA(const int* __restrict__ tokens,
                                          const float* __restrict__ emb,
                                          const float* __restrict__ wih_f,
                                          const float* __restrict__ bih_f,
                                          const float* __restrict__ wih_b,
                                          const float* __restrict__ bih_b)
{
    extern __shared__ float sm[];
    float* s_w = sm;               // 100*290
    float* s_x = sm + 100*290;     // 64*100
    __shared__ int s_tok[64];

    const int dir = blockIdx.y;
    const float* wih = dir ? wih_b : wih_f;
    const float* bih = dir ? bih_b : bih_f;
    const int tid = threadIdx.x;
    const int lane = tid & 31, w = tid >> 5;

    for (int i = tid; i < H3*Eq; i += 256) {
        int j = i / Eq, k = i - j*Eq;
        int p = j >> 5, l = j & 31;
        int idx = (p < 8) ? (k*290 + (p>>1)*64 + l*2 + (p&1)) : (k*290 + 256 + l);
        s_w[idx] = wih[i];
    }
    float bb[9];
#pragma unroll
    for (int p = 0; p < 9; p++) bb[p] = bih[p*32 + lane];

    for (int tile = 0; tile < 8; tile++) {
        const int row0 = (blockIdx.x*8 + tile)*64;
        __syncthreads();               // prev tile's s_x/s_tok reads done
        if (tid < 64) s_tok[tid] = tokens[row0 + tid];
        __syncthreads();
        for (int i = tid; i < 64*Eq; i += 256) {
            int r = i / Eq, k = i - r*Eq;
            s_x[i] = emb[(long long)s_tok[r]*Eq + k];
        }
        __syncthreads();

        ull acc2[8][4];
        float acc1[8];
#pragma unroll
        for (int r = 0; r < 8; r++) {
            acc1[r] = 0.f;
#pragma unroll
            for (int pr = 0; pr < 4; pr++) acc2[r][pr] = 0ull;
        }

        const float* xb = s_x + (w*8)*Eq;
        for (int k = 0; k < Eq; k++) {
            const float* wr = s_w + k*290;
            ull wp0 = *(const ull*)&wr[lane*2];
            ull wp1 = *(const ull*)&wr[64 + lane*2];
            ull wp2 = *(const ull*)&wr[128 + lane*2];
            ull wp3 = *(const ull*)&wr[192 + lane*2];
            float w8 = wr[256 + lane];
#pragma unroll
            for (int r = 0; r < 8; r++) {
                float xv = xb[r*Eq + k];
                ull xd = pack2(xv, xv);
                acc2[r][0] = ffma2(xd, wp0, acc2[r][0]);
                acc2[r][1] = ffma2(xd, wp1, acc2[r][1]);
                acc2[r][2] = ffma2(xd, wp2, acc2[r][2]);
                acc2[r][3] = ffma2(xd, wp3, acc2[r][3]);
                acc1[r] = fmaf(xv, w8, acc1[r]);
            }
        }
#pragma unroll
        for (int r = 0; r < 8; r++) {
            float* go = &g_gi[dir][row0 + w*8 + r][0];
#pragma unroll
            for (int pr = 0; pr < 4; pr++) {
                float2 f = unpack2(acc2[r][pr]);
                go[(2*pr)*32 + lane]   = f.x + bb[2*pr];
                go[(2*pr+1)*32 + lane] = f.y + bb[2*pr+1];
            }
            go[256 + lane] = acc1[r] + bb[8];
        }
    }
}

// ===========================================================================
// Kernel B (unchanged from R11): 128-step GRU scan. 148 CTAs, 128 thr.
// ===========================================================================
template<int NR>
__device__ __forceinline__ void gru_rows(const float* __restrict__ s_whh,
                                         const float* __restrict__ s_bhh,
                                         float* __restrict__ s_h,
                                         int lr0, int t0, int dir, int lane)
{
    ull bh[4]; float bh8;
#pragma unroll
    for (int pr = 0; pr < 4; pr++)
        bh[pr] = pack2(s_bhh[(2*pr)*32 + lane], s_bhh[(2*pr+1)*32 + lane]);
    bh8 = s_bhh[256 + lane];

    for (int s = 0; s < Bq; s++) {
        const int b_eff = dir ? (Bq - 1 - s) : s;
        float gir[NR][9];
#pragma unroll
        for (int j = 0; j < NR; j++) {
            const float* gr = &g_gi[dir][b_eff*Tq + t0 + j][0] + lane;
#pragma unroll
            for (int p = 0; p < 9; p++) gir[j][p] = gr[p*32];
        }

        ull acc2[NR][4];
        float acc1[NR];
#pragma unroll
        for (int j = 0; j < NR; j++) {
            acc1[j] = bh8;
#pragma unroll
            for (int pr = 0; pr < 4; pr++) acc2[j][pr] = bh[pr];
        }

        for (int k0 = 0; k0 < Hq; k0 += 4) {
            float4 h4[NR];
#pragma unroll
            for (int j = 0; j < NR; j++)
                h4[j] = *(const float4*)&s_h[(lr0 + j)*Hq + k0];
#pragma unroll
            for (int kk = 0; kk < 4; kk++) {
                const float* wr = s_whh + (k0 + kk)*290;
                ull wp0 = *(const ull*)&wr[lane*2];
                ull wp1 = *(const ull*)&wr[64 + lane*2];
                ull wp2 = *(const ull*)&wr[128 + lane*2];
                ull wp3 = *(const ull*)&wr[192 + lane*2];
                float w8 = wr[256 + lane];
#pragma unroll
                for (int j = 0; j < NR; j++) {
                    float hv = ((const float*)&h4[j])[kk];
                    ull hd = pack2(hv, hv);
                    acc2[j][0] = ffma2(hd, wp0, acc2[j][0]);
                    acc2[j][1] = ffma2(hd, wp1, acc2[j][1]);
                    acc2[j][2] = ffma2(hd, wp2, acc2[j][2]);
                    acc2[j][3] = ffma2(hd, wp3, acc2[j][3]);
                    acc1[j] = fmaf(hv, w8, acc1[j]);
                }
            }
        }
        __syncwarp();
#pragma unroll
        for (int j = 0; j < NR; j++) {
            float a9[9];
#pragma unroll
            for (int pr = 0; pr < 4; pr++) {
                float2 f = unpack2(acc2[j][pr]);
                a9[2*pr] = f.x; a9[2*pr+1] = f.y;
            }
            a9[8] = acc1[j];
            const int lr = lr0 + j;
            float* hout = &g_h[b_eff*Tq + t0 + j][dir*Hq];
#pragma unroll
            for (int g = 0; g < 3; g++) {
                const int u = g*32 + lane;
                float rg = sigm_f(gir[j][g]   + a9[g]);
                float zg = sigm_f(gir[j][3+g] + a9[3+g]);
                float ng = tanh_f(gir[j][6+g] + rg*a9[6+g]);
                float ho = s_h[lr*Hq + u];
                float h2 = ng + zg*(ho - ng);
                s_h[lr*Hq + u] = h2;
                hout[u] = h2;
            }
        }
        __syncwarp();
    }
}

__global__ __launch_bounds__(128) void kB(const float* __restrict__ whh_f,
                                          const float* __restrict__ bhh_f,
                                          const float* __restrict__ whh_b,
                                          const float* __restrict__ bhh_b)
{
    extern __shared__ float sm[];
    float* s_whh = sm;                 // 96*290
    float* s_bhh = sm + Hq*290;        // 288
    float* s_h   = s_bhh + H3;         // 12*96
    const int dir = blockIdx.x / 74;
    const int ci  = blockIdx.x % 74;
    const int base  = ci*10 + (ci < 60 ? ci : 60);
    const int count = 10 + (ci < 60 ? 1 : 0);
    const float* whh = dir ? whh_b : whh_f;
    const float* bhh = dir ? bhh_b : bhh_f;
    const int tid = threadIdx.x;

    for (int i = tid; i < H3*Hq; i += 128) {
        int j = i / Hq, k = i - j*Hq;
        int p = j >> 5, l = j & 31;
        int idx = (p < 8) ? (k*290 + (p>>1)*64 + l*2 + (p&1)) : (k*290 + 256 + l);
        s_whh[idx] = whh[i];
    }
    for (int i = tid; i < H3; i += 128) s_bhh[i] = bhh[i];
    for (int i = tid; i < 12*Hq; i += 128) s_h[i] = 0.f;
    __syncthreads();

    const int w = tid >> 5, lane = tid & 31;
    const int q = count >> 2, rem = count & 3;
    const int w_off = w*q + (w < rem ? w : rem);
    const int nr = q + (w < rem ? 1 : 0);
    if (nr == 3) gru_rows<3>(s_whh, s_bhh, s_h, w_off, base + w_off, dir, lane);
    else         gru_rows<2>(s_whh, s_bhh, s_h, w_off, base + w_off, dir, lane);
}

// ===========================================================================
// Kernel C: attention + m + gram + squash -> v0T, attreg. 128 CTAs, 256 thr.
// h tile stored TRANSPOSED s_hT[k][row] (pitch 66) -> GEMM1 row-pair operand
// is one broadcast LDS.64.
// ===========================================================================
__global__ __launch_bounds__(256) void kC(const float* __restrict__ A1,
                                          const float* __restrict__ b1,
                                          const float* __restrict__ A2,
                                          const float* __restrict__ b2)
{
    extern __shared__ float sm[];
    float* A1s = sm;                       // 9600
    float* A2s = A1s + 9600;               // 600
    float* b1s = A2s + 600;                // 52
    float* b2s = b1s + 52;                 // 16
    float* s_hT = b2s + 16;                // 192*66 = 12672  [k][row], pitch 66
    float* s_P  = s_hT + 12672;            // 64*53
    float* s_a  = s_P + 3392;              // 64*12
    float* m_s  = s_a + 768;               // 2304
    float* G_s  = m_s + 2304;              // 144

    const int b = blockIdx.x, tid = threadIdx.x;
    const int lane = tid & 31, w = tid >> 5;

    for (int i = tid; i < 9600; i += 256) A1s[i] = A1[i];
    for (int i = tid; i < 600;  i += 256) A2s[i] = A2[i];
    if (tid < 50) b1s[tid] = b1[tid];
    if (tid < 12) b2s[tid] = b2[tid];
    if (tid < 144) G_s[tid] = 0.f;

    float accm[12];
#pragma unroll
    for (int r = 0; r < 12; r++) accm[r] = 0.f;

    for (int t0 = 0; t0 < Tq; t0 += 64) {
        const int nrows = (Tq - t0 < 64) ? (Tq - t0) : 64;
        __syncthreads();
        const float4* h4s = (const float4*)&g_h[b*Tq + t0][0];
        for (int i = tid; i < nrows*48; i += 256) {
            int row = i / 48, k4 = i - row*48;
            float4 v = h4s[i];
            float* dst = s_hT + (k4*4)*66 + row;
            dst[0]   = v.x;
            dst[66]  = v.y;
            dst[132] = v.z;
            dst[198] = v.w;
        }
        __syncthreads();

        // GEMM1: P = tanh(h @ A1 + b1), row pairs via f32x2; h pair = LDS.64 bcast
        {
            const int rbase = w*8;
            if (rbase < nrows) {
                ull acc0p[4], acc1p[4];
#pragma unroll
                for (int pr = 0; pr < 4; pr++) { acc0p[pr] = 0ull; acc1p[pr] = 0ull; }
                for (int k = 0; k < 192; k++) {
                    float a0 = A1s[k*50 + lane];
                    float a1 = (lane < 18) ? A1s[k*50 + lane + 32] : 0.f;
                    ull a0d = pack2(a0, a0), a1d = pack2(a1, a1);
                    const ull* hrow = (const ull*)(s_hT + k*66 + rbase);
#pragma unroll
                    for (int pr = 0; pr < 4; pr++) {
                        ull hp = hrow[pr];
                        acc0p[pr] = ffma2(hp, a0d, acc0p[pr]);
                        acc1p[pr] = ffma2(hp, a1d, acc1p[pr]);
                    }
                }
#pragma unroll
                for (int pr = 0; pr < 4; pr++) {
                    float2 f0 = unpack2(acc0p[pr]);
                    float2 f1 = unpack2(acc1p[pr]);
                    int r0 = rbase + 2*pr, r1 = r0 + 1;
                    if (r0 < nrows) {
                        s_P[r0*53 + lane] = tanh_f(f0.x + b1s[lane]);
                        if (lane < 18) s_P[r0*53 + lane + 32] = tanh_f(f1.x + b1s[lane+32]);
                    }
                    if (r1 < nrows) {
                        s_P[r1*53 + lane] = tanh_f(f0.y + b1s[lane]);
                        if (lane < 18) s_P[r1*53 + lane + 32] = tanh_f(f1.y + b1s[lane+32]);
                    }
                }
            }
        }
        __syncthreads();

        for (int i = tid; i < nrows*12; i += 256) {
            int t = i / 12, r = i - t*12;
            float s = b2s[r];
            for (int k = 0; k < 50; k++) s = fmaf(s_P[t*53 + k], A2s[k*12 + r], s);
            s_a[t*12 + r] = s;
        }
        __syncthreads();

        if (tid < nrows) {
            float* ar = s_a + tid*12;
            float mx = ar[0];
#pragma unroll
            for (int r = 1; r < 12; r++) mx = fmaxf(mx, ar[r]);
            float ss = 0.f;
#pragma unroll
            for (int r = 0; r < 12; r++) { float e = __expf(ar[r]-mx); ar[r] = e; ss += e; }
            float inv = 1.f/ss;
#pragma unroll
            for (int r = 0; r < 12; r++) ar[r] *= inv;
        }
        __syncthreads();

        if (tid < 192) {
            for (int lt = 0; lt < nrows; lt++) {
                float hv = s_hT[tid*66 + lt];
                const float4* a4 = (const float4*)(s_a + lt*12);
                float4 c0 = a4[0], c1 = a4[1], c2 = a4[2];
                accm[0]  = fmaf(c0.x, hv, accm[0]);
                accm[1]  = fmaf(c0.y, hv, accm[1]);
                accm[2]  = fmaf(c0.z, hv, accm[2]);
                accm[3]  = fmaf(c0.w, hv, accm[3]);
                accm[4]  = fmaf(c1.x, hv, accm[4]);
                accm[5]  = fmaf(c1.y, hv, accm[5]);
                accm[6]  = fmaf(c1.z, hv, accm[6]);
                accm[7]  = fmaf(c1.w, hv, accm[7]);
                accm[8]  = fmaf(c2.x, hv, accm[8]);
                accm[9]  = fmaf(c2.y, hv, accm[9]);
                accm[10] = fmaf(c2.z, hv, accm[10]);
                accm[11] = fmaf(c2.w, hv, accm[11]);
            }
        } else {
            for (int ii = tid - 192; ii < 144; ii += 64) {
                int r = ii / 12, s2 = ii - r*12;
                float g = 0.f;
                for (int lt = 0; lt < nrows; lt++)
                    g = fmaf(s_a[lt*12 + r], s_a[lt*12 + s2], g);
                G_s[ii] += g;
            }
        }
    }
    __syncthreads();
    if (tid < 192)
#pragma unroll
        for (int r = 0; r < 12; r++) m_s[r*192 + tid] = accm[r];
    __syncthreads();

    for (int r = w; r < 12; r += 8) {
        float s = 0.f;
        for (int k = lane; k < 192; k += 32) { float x = m_s[r*192+k]; s = fmaf(x,x,s); }
#pragma unroll
        for (int off = 16; off; off >>= 1) s += __shfl_xor_sync(0xffffffffu, s, off);
        float sc = s/(s + 1.f)*rsqrtf(s);
        for (int k = lane; k < 192; k += 32)
            g_v0T[r*192 + k][b] = m_s[r*192+k]*sc;
    }
    if (tid < 144) {
        int r = tid / 12, s2 = tid - r*12;
        float d = G_s[tid] - (r == s2 ? 1.f : 0.f);
        G_s[tid] = d*d;
    }
    __syncthreads();
    if (tid == 0) {
        float s = 0.f;
        for (int i = 0; i < 144; i++) s += G_s[i];
        g_attreg[b] = sqrtf(s);
    }
}

// ===========================================================================
// Kernel D (unchanged): u_hat = v0 @ Wcaps per r. grid(20,12), 256 thr, f32x2.
// ===========================================================================
__global__ __launch_bounds__(256) void kD(const float* __restrict__ Wcaps)
{
    extern __shared__ float sm[];
    float* s_w = sm;                // 192*40
    float* s_v = sm + 192*40;       // 64*128
    const int cch = blockIdx.x, r = blockIdx.y;
    const int tid = threadIdx.x;
    const int b = tid & 127, half = tid >> 7;
    const int lane = tid & 31, w = tid >> 5;

    for (int k = w; k < 192; k += 8) {
        const float* src = Wcaps + (long long)(r*192 + k)*800 + cch*40;
        for (int off = lane; off < 40; off += 32) s_w[k*40 + off] = src[off];
    }

    ull acc2[10];
#pragma unroll
    for (int q = 0; q < 10; q++) acc2[q] = 0ull;

    for (int kc = 0; kc < 3; kc++) {
        __syncthreads();
        for (int i = tid; i < 64*128; i += 256)
            s_v[i] = g_v0T[r*192 + kc*64 + (i >> 7)][i & 127];
        __syncthreads();
#pragma unroll 4
        for (int k2 = 0; k2 < 64; k2++) {
            float vv = s_v[k2*128 + b];
            ull vd = pack2(vv, vv);
            const ulonglong2* w2 = (const ulonglong2*)(s_w + (kc*64 + k2)*40 + half*20);
#pragma unroll
            for (int q = 0; q < 5; q++) {
                ulonglong2 wv = w2[q];
                acc2[2*q]   = ffma2(vd, wv.x, acc2[2*q]);
                acc2[2*q+1] = ffma2(vd, wv.y, acc2[2*q+1]);
            }
        }
    }
    float* up = &g_uhat[b][r*800 + cch*40 + half*20];
#pragma unroll
    for (int q = 0; q < 10; q++) {
        float2 f = unpack2(acc2[q]);
        up[2*q] = f.x; up[2*q+1] = f.y;
    }
}

// ===========================================================================
// Kernel E (unchanged): 3-iter dynamic routing in smem + output. 128 CTAs.
// ===========================================================================
__global__ __launch_bounds__(256) void kE(float* __restrict__ out, int out_size)
{
    extern __shared__ float sm[];
    float* u   = sm;            // 9600
    float* bl  = u + 9600;      // 600
    float* cc  = bl + 600;      // 600
    float* s_s = cc + 600;      // 800
    float* s_v = s_s + 800;     // 800
    float* s_n = s_v + 800;     // 50

    const int b = blockIdx.x, tid = threadIdx.x;
    const float4* u4 = (const float4*)&g_uhat[b][0];
    float4* su4 = (float4*)u;
    for (int i = tid; i < 2400; i += 256) su4[i] = u4[i];
    for (int i = tid; i < 600; i += 256) bl[i] = 0.f;
    __syncthreads();

    for (int it = 0; it < 3; it++) {
        if (tid < 12) {
            const float* br = bl + tid*50;
            float mx = br[0];
            for (int k = 1; k < 50; k++) mx = fmaxf(mx, br[k]);
            float ss = 0.f;
            for (int k = 0; k < 50; k++) { float e = __expf(br[k]-mx); cc[tid*50+k] = e; ss += e; }
            float inv = 1.f/ss;
            for (int k = 0; k < 50; k++) cc[tid*50+k] *= inv;
        }
        __syncthreads();
        for (int i = tid; i < 800; i += 256) {
            int ci = i >> 4, o = i & 15;
            float s = 0.f;
#pragma unroll
            for (int r = 0; r < 12; r++)
                s = fmaf(cc[r*50 + ci], u[(r*50 + ci)*16 + o], s);
            s_s[i] = s;
        }
        __syncthreads();
        if (tid < 50) {
            float n = 0.f;
#pragma unroll
            for (int o = 0; o < 16; o++) { float x = s_s[tid*16+o]; n = fmaf(x,x,n); }
            s_n[tid] = n/(n + 1.f)*rsqrtf(n);
        }
        __syncthreads();
        for (int i = tid; i < 800; i += 256) s_v[i] = s_s[i]*s_n[i >> 4];
        __syncthreads();
        if (it != 2) {
            for (int i = tid; i < 600; i += 256) {
                int r = i / 50, ci = i - r*50;
                float s = 0.f;
#pragma unroll
                for (int o = 0; o < 16; o++)
                    s = fmaf(u[(r*50 + ci)*16 + o], s_v[ci*16 + o], s);
                bl[i] += s;
            }
            __syncthreads();
        }
    }
    for (int i = tid; i < 800; i += 256) out[b*800 + i] = s_v[i];

    if (b == 0 && tid == 0 && out_size > Bq*800) {
        float s = 0.f;
        for (int i = 0; i < Bq; i++) s += g_attreg[i];
        out[Bq*800] = s / Bq;
    }
}

// ===========================================================================
extern "C" void kernel_launch(void* const* d_in, const int* in_sizes, int n_in,
                              void* d_out, int out_size)
{
    const int*   tokens = (const int*)  d_in[0];
    const float* emb    = (const float*)d_in[1];
    const float* wih_f  = (const float*)d_in[2];
    const float* whh_f  = (const float*)d_in[3];
    const float* bih_f  = (const float*)d_in[4];
    const float* bhh_f  = (const float*)d_in[5];
    const float* wih_b  = (const float*)d_in[6];
    const float* whh_b  = (const float*)d_in[7];
    const float* bih_b  = (const float*)d_in[8];
    const float* bhh_b  = (const float*)d_in[9];
    const float* A1     = (const float*)d_in[10];
    const float* b1     = (const float*)d_in[11];
    const float* A2     = (const float*)d_in[12];
    const float* b2     = (const float*)d_in[13];
    const float* Wcaps  = (const float*)d_in[14];
    float* out = (float*)d_out;

    const int smA = (100*290 + 64*100)*4;
    const int smB = (96*290 + 288 + 12*96)*4;
    const int smC = (9600+600+52+16+12672+3392+768+2304+144)*4;
    const int smD = (192*40 + 64*128)*4;
    const int smE = (9600+600+600+800+800+50)*4;

    cudaFuncSetAttribute(kA, cudaFuncAttributeMaxDynamicSharedMemorySize, smA);
    cudaFuncSetAttribute(kB, cudaFuncAttributeMaxDynamicSharedMemorySize, smB);
    cudaFuncSetAttribute(kC, cudaFuncAttributeMaxDynamicSharedMemorySize, smC);
    cudaFuncSetAttribute(kD, cudaFuncAttributeMaxDynamicSharedMemorySize, smD);
    cudaFuncSetAttribute(kE, cudaFuncAttributeMaxDynamicSharedMemorySize, smE);

    kA<<<dim3(200, 2), 256, smA>>>(tokens, emb, wih_f, bih_f, wih_b, bih_b);
    kB<<<148, 128, smB>>>(whh_f, bhh_f, whh_b, bhh_b);
    kC<<<128, 256, smC>>>(A1, b1, A2, b2);
    kD<<<dim3(20, 12), 256, smD>>>(Wcaps);
    kE<<<128, 256, smE>>>(out, out_size);
}